// round 6
// baseline (speedup 1.0000x reference)
#include <cuda_runtime.h>
#include <cstdint>
#include <cstddef>

// TensorFusion: B=32, N=4096, C=16, D=256
//   out[b,c,d]  = (1/N) * sum_n [r[b,n,c] >= 0.5] * v[b,n,d]        c in 0..15
//   out[b,16,d] = (1/N) * sum_n [all c: r[b,n,c] < 0.5] * v[b,n,d]

#define B_DIM 32
#define N_DIM 4096
#define C_DIM 16
#define D_DIM 256
#define OUT_C (C_DIM + 1)

#define SPLIT 16
#define NCHUNK (N_DIM / SPLIT)   // 256 rows per CTA
#define THREADS 256

__global__ void tf_zero_kernel(float* __restrict__ out, int n) {
    int i = blockIdx.x * blockDim.x + threadIdx.x;
    if (i < n) out[i] = 0.0f;
}

__global__ __launch_bounds__(THREADS, 4)
void tf_fusion_kernel(const float* __restrict__ r,
                      const float* __restrict__ v,
                      float* __restrict__ out) {
    __shared__ unsigned smem_mask[NCHUNK];

    const int b  = blockIdx.y;
    const int n0 = blockIdx.x * NCHUNK;
    const int t  = threadIdx.x;

    // ---- Phase A: one mask word per row of this chunk (thread t -> row t) ----
    {
        const float4* rp = reinterpret_cast<const float4*>(
            r + (size_t)(b * N_DIM + n0 + t) * C_DIM);
        unsigned m = 0u;
        #pragma unroll
        for (int j = 0; j < 4; ++j) {
            float4 x = rp[j];
            m |= (x.x >= 0.5f ? 1u : 0u) << (4 * j + 0);
            m |= (x.y >= 0.5f ? 1u : 0u) << (4 * j + 1);
            m |= (x.z >= 0.5f ? 1u : 0u) << (4 * j + 2);
            m |= (x.w >= 0.5f ? 1u : 0u) << (4 * j + 3);
        }
        if (m == 0u) m = 1u << 16;   // "special" channel: no category matched
        smem_mask[t] = m;
    }
    __syncthreads();

    // ---- Phase B: thread t owns output column d = t; stream 256 rows of v ----
    float acc[OUT_C];
    #pragma unroll
    for (int c = 0; c < OUT_C; ++c) acc[c] = 0.0f;

    const float* vp = v + (size_t)(b * N_DIM + n0) * D_DIM + t;

    #pragma unroll 1
    for (int n = 0; n < NCHUNK; n += 4) {
        // batch the 4 independent global loads up front (MLP)
        float val0 = vp[(size_t)(n + 0) * D_DIM];
        float val1 = vp[(size_t)(n + 1) * D_DIM];
        float val2 = vp[(size_t)(n + 2) * D_DIM];
        float val3 = vp[(size_t)(n + 3) * D_DIM];
        unsigned m0 = smem_mask[n + 0];
        unsigned m1 = smem_mask[n + 1];
        unsigned m2 = smem_mask[n + 2];
        unsigned m3 = smem_mask[n + 3];
        #pragma unroll
        for (int c = 0; c < OUT_C; ++c) {
            const unsigned bit = 1u << c;
            if (m0 & bit) acc[c] += val0;
            if (m1 & bit) acc[c] += val1;
            if (m2 & bit) acc[c] += val2;
            if (m3 & bit) acc[c] += val3;
        }
    }

    // ---- Phase C: scale + atomic reduction into the output ----
    const float scale = 1.0f / (float)N_DIM;
    float* op = out + (size_t)b * OUT_C * D_DIM + t;
    #pragma unroll
    for (int c = 0; c < OUT_C; ++c) {
        atomicAdd(op + c * D_DIM, acc[c] * scale);
    }
}

extern "C" void kernel_launch(void* const* d_in, const int* in_sizes, int n_in,
                              void* d_out, int out_size) {
    // Inputs per metadata order: r_tensor (B*N*C), v_tensor (B*N*D).
    // Disambiguate defensively by element count.
    const float* r = (const float*)d_in[0];
    const float* v = (const float*)d_in[1];
    if (n_in >= 2 && in_sizes[0] == B_DIM * N_DIM * D_DIM &&
        in_sizes[1] == B_DIM * N_DIM * C_DIM) {
        r = (const float*)d_in[1];
        v = (const float*)d_in[0];
    }
    float* out = (float*)d_out;

    const int out_elems = B_DIM * OUT_C * D_DIM;  // 139264
    tf_zero_kernel<<<(out_elems + 255) / 256, 256>>>(out, out_elems);

    dim3 grid(SPLIT, B_DIM);
    tf_fusion_kernel<<<grid, THREADS>>>(r, v, out);
}